// round 13
// baseline (speedup 1.0000x reference)
#include <cuda_runtime.h>
#include <cuda_fp16.h>
#include <cuda_bf16.h>
#include <cfloat>

#define N_MAX 50000
#define E_MAX 800000
#define PB_MAX ((N_MAX + 7) / 8)
#define LRELU 0.2f
#define ENC_NEGINF 0x007FFFFFu

// ---------------- device scratch ----------------
__device__ __half g_hh[N_MAX * 256];   // layer-1 message features fp16
__device__ __half g_x1h[N_MAX * 256];  // layer-0 output fp16 (node1mma A operand)
__device__ __half g_W1h[256 * 256];    // W1 transposed (n-major), fp16
__device__ float g_x1[N_MAX * 256];    // final layer output (fp32, pooling consumers)
__device__ float g_als[N_MAX * 4];
__device__ float g_ald[N_MAX * 4];
__device__ float g_p[E_MAX * 4];       // attention weights fp32, CSR order
__device__ int   g_deg[N_MAX];
__device__ int   g_offs[N_MAX];
__device__ int   g_cursor[N_MAX];
__device__ int   g_srcPerm[E_MAX];
__device__ int   g_epos[E_MAX];
__device__ int   g_bsum[64];
__device__ int   g_bsumScan[64];
__device__ float g_poolSum[PB_MAX * 256];
__device__ float g_poolMax[PB_MAX * 256];

__device__ float g_asEff0[5 * 4], g_adEff0[5 * 4], g_aeEff0[4 * 4], g_selfae0[4];
__device__ float g_aeEff1[4 * 4], g_selfae1[4];
__device__ float g_meanRaw[4];

__device__ float    g_meansum[256];
__device__ unsigned g_maxbits[256];
__device__ float    g_attsum[256];
__device__ float    g_s[N_MAX];
__device__ float    g_pn[N_MAX];
__device__ unsigned g_smaxbits;
__device__ float    g_Z;

// ---------------- helpers ----------------
__device__ __forceinline__ unsigned encf(float f) {
    unsigned b = __float_as_uint(f);
    return (b & 0x80000000u) ? ~b : (b | 0x80000000u);
}
__device__ __forceinline__ float decf(unsigned u) {
    return (u & 0x80000000u) ? __uint_as_float(u ^ 0x80000000u) : __uint_as_float(~u);
}
__device__ __forceinline__ float lrelu(float a) { return a > 0.f ? a : LRELU * a; }

__device__ __forceinline__ void acc8(float& a0, float& a1, float& a2, float& a3,
                                     float& a4, float& a5, float& a6, float& a7,
                                     uint4 u, float p) {
    float2 f;
    f = __half22float2(*(const __half2*)&u.x); a0 += p * f.x; a1 += p * f.y;
    f = __half22float2(*(const __half2*)&u.y); a2 += p * f.x; a3 += p * f.y;
    f = __half22float2(*(const __half2*)&u.z); a4 += p * f.x; a5 += p * f.y;
    f = __half22float2(*(const __half2*)&u.w); a6 += p * f.x; a7 += p * f.y;
}

__device__ __forceinline__ void mma16816(float& c0, float& c1, float& c2, float& c3,
                                         unsigned a0, unsigned a1, unsigned a2, unsigned a3,
                                         unsigned b0, unsigned b1) {
    asm volatile(
        "mma.sync.aligned.m16n8k16.row.col.f32.f16.f16.f32 "
        "{%0,%1,%2,%3}, {%4,%5,%6,%7}, {%8,%9}, {%0,%1,%2,%3};"
        : "+f"(c0), "+f"(c1), "+f"(c2), "+f"(c3)
        : "r"(a0), "r"(a1), "r"(a2), "r"(a3), "r"(b0), "r"(b1));
}

// ---------------- setup kernels ----------------
__global__ void k_zero(int N) {
    int i = blockIdx.x * blockDim.x + threadIdx.x;
    if (i < N) { g_deg[i] = 0; g_cursor[i] = 0; }
    if (i < 256) { g_meansum[i] = 0.f; g_attsum[i] = 0.f; g_maxbits[i] = ENC_NEGINF; }
    if (i < 4) g_meanRaw[i] = 0.f;
    if (i == 0) { g_Z = 0.f; g_smaxbits = ENC_NEGINF; }
}

__global__ void k_meanEA(const float* __restrict__ ea, int E) {
    __shared__ float sm[256][4];
    float a0 = 0, a1 = 0, a2 = 0, a3 = 0;
    int stride = gridDim.x * blockDim.x;
    for (int e = blockIdx.x * blockDim.x + threadIdx.x; e < E; e += stride) {
        float4 v = ((const float4*)ea)[e];
        a0 += v.x; a1 += v.y; a2 += v.z; a3 += v.w;
    }
    sm[threadIdx.x][0] = a0; sm[threadIdx.x][1] = a1;
    sm[threadIdx.x][2] = a2; sm[threadIdx.x][3] = a3;
    __syncthreads();
    for (int s = 128; s > 0; s >>= 1) {
        if (threadIdx.x < s) {
            sm[threadIdx.x][0] += sm[threadIdx.x + s][0];
            sm[threadIdx.x][1] += sm[threadIdx.x + s][1];
            sm[threadIdx.x][2] += sm[threadIdx.x + s][2];
            sm[threadIdx.x][3] += sm[threadIdx.x + s][3];
        }
        __syncthreads();
    }
    if (threadIdx.x < 4) atomicAdd(&g_meanRaw[threadIdx.x], sm[0][threadIdx.x]);
}

__global__ void k_deg(const int* __restrict__ dst, int E) {
    int e = blockIdx.x * blockDim.x + threadIdx.x;
    if (e < E) atomicAdd(&g_deg[dst[e]], 1);
}

__global__ void k_scanA(int N) {
    __shared__ int sm[1024];
    int i = blockIdx.x * 1024 + threadIdx.x;
    int v = (i < N) ? g_deg[i] : 0;
    sm[threadIdx.x] = v;
    __syncthreads();
    for (int d = 1; d < 1024; d <<= 1) {
        int t = (threadIdx.x >= d) ? sm[threadIdx.x - d] : 0;
        __syncthreads();
        sm[threadIdx.x] += t;
        __syncthreads();
    }
    if (i < N) g_offs[i] = sm[threadIdx.x] - v;
    if (threadIdx.x == 1023) g_bsum[blockIdx.x] = sm[1023];
}

__global__ void k_scanB(int NB) {
    __shared__ int sm[64];
    int t = threadIdx.x;
    int orig = (t < NB) ? g_bsum[t] : 0;
    sm[t] = orig;
    __syncthreads();
    for (int d = 1; d < 64; d <<= 1) {
        int v = (t >= d) ? sm[t - d] : 0;
        __syncthreads();
        sm[t] += v;
        __syncthreads();
    }
    g_bsumScan[t] = sm[t] - orig;
}

__global__ void k_scanC(int N) {
    int i = blockIdx.x * 1024 + threadIdx.x;
    if (i < N) g_offs[i] += g_bsumScan[blockIdx.x];
}

__global__ void k_place(const int* __restrict__ src, const int* __restrict__ dst, int E) {
    int e = blockIdx.x * blockDim.x + threadIdx.x;
    if (e < E) {
        int d = dst[e];
        int pos = g_offs[d] + atomicAdd(&g_cursor[d], 1);
        g_epos[e] = pos;
        g_srcPerm[pos] = src[e];
    }
}

__global__ void k_w1h(const float* __restrict__ W1) {
    int idx = blockIdx.x * 256 + threadIdx.x;
    int k = idx >> 8, n = idx & 255;
    g_W1h[n * 256 + k] = __float2half_rn(W1[k * 256 + n]);
}

__global__ void k_pre(const float* __restrict__ W0, const float* __restrict__ as0,
                      const float* __restrict__ ad0, const float* __restrict__ We0,
                      const float* __restrict__ ae0,
                      const float* __restrict__ We1, const float* __restrict__ ae1,
                      float Ef) {
    __shared__ float sm_mean[4];
    int tid = threadIdx.x;
    for (int idx = tid; idx < 20; idx += 256) {
        int k = idx >> 2, h = idx & 3;
        float s1 = 0, s2 = 0;
        for (int c = 0; c < 64; c++) {
            float w = W0[k * 256 + h * 64 + c];
            s1 += w * as0[h * 64 + c]; s2 += w * ad0[h * 64 + c];
        }
        g_asEff0[idx] = s1; g_adEff0[idx] = s2;
    }
    for (int idx = tid; idx < 16; idx += 256) {
        int k = idx >> 2, h = idx & 3;
        float s0 = 0, s1 = 0;
        for (int c = 0; c < 64; c++) {
            s0 += We0[k * 256 + h * 64 + c] * ae0[h * 64 + c];
            s1 += We1[k * 256 + h * 64 + c] * ae1[h * 64 + c];
        }
        g_aeEff0[idx] = s0; g_aeEff1[idx] = s1;
    }
    __syncthreads();
    if (tid < 4) sm_mean[tid] = g_meanRaw[tid] / Ef;
    __syncthreads();
    if (tid < 4) {
        float s0 = 0, s1 = 0;
        for (int k = 0; k < 4; k++) {
            s0 += sm_mean[k] * g_aeEff0[k * 4 + tid];
            s1 += sm_mean[k] * g_aeEff1[k * 4 + tid];
        }
        g_selfae0[tid] = s0; g_selfae1[tid] = s1;
    }
}

// ---------------- layer 0: attention logits only (h0 never materialized) ----------------
__global__ void k_node0b(const float* __restrict__ x, int N) {
    int idx = blockIdx.x * blockDim.x + threadIdx.x;
    int n = idx >> 3;
    if (n >= N) return;
    int t = idx & 7;
    int which = t >> 2, h = t & 3;
    float xk[5];
#pragma unroll
    for (int k = 0; k < 5; k++) xk[k] = x[n * 5 + k];
    const float* eff = which ? g_adEff0 : g_asEff0;
    float a = 0.f;
#pragma unroll
    for (int k = 0; k < 5; k++) a += xk[k] * eff[k * 4 + h];
    (which ? g_ald : g_als)[n * 4 + h] = a;
}

// ---------------- per-edge attention weights (written in CSR order) ----------------
template <int L>
__global__ void k_edge(const int* __restrict__ src, const int* __restrict__ dst,
                       const float* __restrict__ ea, int E) {
    int e = blockIdx.x * blockDim.x + threadIdx.x;
    if (e >= E) return;
    const float* aeEff = L ? g_aeEff1 : g_aeEff0;
    float4 v = ((const float4*)ea)[e];
    int s = src[e], d = dst[e];
    float4 as = ((const float4*)g_als)[s];
    float4 ad = ((const float4*)g_ald)[d];
    float4 p;
    float ale;
    ale = v.x * aeEff[0] + v.y * aeEff[4] + v.z * aeEff[8] + v.w * aeEff[12];
    p.x = __expf(lrelu(as.x + ad.x + ale));
    ale = v.x * aeEff[1] + v.y * aeEff[5] + v.z * aeEff[9] + v.w * aeEff[13];
    p.y = __expf(lrelu(as.y + ad.y + ale));
    ale = v.x * aeEff[2] + v.y * aeEff[6] + v.z * aeEff[10] + v.w * aeEff[14];
    p.z = __expf(lrelu(as.z + ad.z + ale));
    ale = v.x * aeEff[3] + v.y * aeEff[7] + v.z * aeEff[11] + v.w * aeEff[15];
    p.w = __expf(lrelu(as.w + ad.w + ale));
    ((float4*)g_p)[g_epos[e]] = p;
}

// ---------------- layer-0 gather in x-space: warp/node, lane-per-edge ----------------
// out[h,:] = ((pself*x[n] + sum_e p_e[h]*x[src_e]) / denom[h]) @ W0[:, h*64:...] + b0, relu
__global__ __launch_bounds__(256) void k_gather0(const float* __restrict__ x,
                                                 const float* __restrict__ W0,
                                                 const float* __restrict__ b, int N) {
    int wib = threadIdx.x >> 5;
    int lane = threadIdx.x & 31;
    int n = blockIdx.x * 8 + wib;
    if (n >= N) return;
    float acc[4][5];
    float den[4];
#pragma unroll
    for (int h = 0; h < 4; h++) {
        den[h] = 0.f;
#pragma unroll
        for (int k = 0; k < 5; k++) acc[h][k] = 0.f;
    }
    int base = g_offs[n], deg = g_deg[n];
    for (int i = lane; i < deg; i += 32) {
        int e = base + i;
        int s = g_srcPerm[e];
        float4 p4 = ((const float4*)g_p)[e];
        float xk[5];
#pragma unroll
        for (int k = 0; k < 5; k++) xk[k] = x[s * 5 + k];
#pragma unroll
        for (int k = 0; k < 5; k++) {
            acc[0][k] += p4.x * xk[k];
            acc[1][k] += p4.y * xk[k];
            acc[2][k] += p4.z * xk[k];
            acc[3][k] += p4.w * xk[k];
        }
        den[0] += p4.x; den[1] += p4.y; den[2] += p4.z; den[3] += p4.w;
    }
    if (lane == 0) {
        // self loop
        float xk[5];
#pragma unroll
        for (int k = 0; k < 5; k++) xk[k] = x[n * 5 + k];
#pragma unroll
        for (int h = 0; h < 4; h++) {
            float ps = __expf(lrelu(g_als[n * 4 + h] + g_ald[n * 4 + h] + g_selfae0[h]));
            den[h] += ps;
#pragma unroll
            for (int k = 0; k < 5; k++) acc[h][k] += ps * xk[k];
        }
    }
    // butterfly all-reduce of 24 values
#pragma unroll
    for (int o = 16; o > 0; o >>= 1) {
#pragma unroll
        for (int h = 0; h < 4; h++) {
            den[h] += __shfl_xor_sync(0xFFFFFFFFu, den[h], o);
#pragma unroll
            for (int k = 0; k < 5; k++)
                acc[h][k] += __shfl_xor_sync(0xFFFFFFFFu, acc[h][k], o);
        }
    }
    int hh = lane >> 3;
    // select this lane's head accumulator (compile-time indices only)
    float a0, a1, a2, a3, a4, dd;
    if (hh == 0)      { a0 = acc[0][0]; a1 = acc[0][1]; a2 = acc[0][2]; a3 = acc[0][3]; a4 = acc[0][4]; dd = den[0]; }
    else if (hh == 1) { a0 = acc[1][0]; a1 = acc[1][1]; a2 = acc[1][2]; a3 = acc[1][3]; a4 = acc[1][4]; dd = den[1]; }
    else if (hh == 2) { a0 = acc[2][0]; a1 = acc[2][1]; a2 = acc[2][2]; a3 = acc[2][3]; a4 = acc[2][4]; dd = den[2]; }
    else              { a0 = acc[3][0]; a1 = acc[3][1]; a2 = acc[3][2]; a3 = acc[3][3]; a4 = acc[3][4]; dd = den[3]; }
    float inv = 1.f / (dd + 1e-16f);
    a0 *= inv; a1 *= inv; a2 *= inv; a3 *= inv; a4 *= inv;
    int c0 = lane * 8;
    float o[8];
#pragma unroll
    for (int j = 0; j < 8; j++) {
        int c = c0 + j;
        float s = a0 * W0[c] + a1 * W0[256 + c] + a2 * W0[512 + c] +
                  a3 * W0[768 + c] + a4 * W0[1024 + c];
        o[j] = fmaxf(s + b[c], 0.f);
    }
    __half2 q0 = __floats2half2_rn(o[0], o[1]), q1 = __floats2half2_rn(o[2], o[3]);
    __half2 q2 = __floats2half2_rn(o[4], o[5]), q3 = __floats2half2_rn(o[6], o[7]);
    uint4 pk;
    pk.x = *(unsigned*)&q0; pk.y = *(unsigned*)&q1;
    pk.z = *(unsigned*)&q2; pk.w = *(unsigned*)&q3;
    ((uint4*)(g_x1h + (size_t)n * 256))[lane] = pk;
}

// ---------------- layer-1 gather (R7, unchanged) ----------------
template <int L>
__global__ __launch_bounds__(256) void k_gather(const float* __restrict__ b, int N) {
    int wib = threadIdx.x >> 5;
    int lane = threadIdx.x & 31;
    int n = blockIdx.x * 8 + wib;
    int hh = lane >> 3;
    bool active = (n < N);
    float o0 = 0, o1 = 0, o2 = 0, o3 = 0, o4 = 0, o5 = 0, o6 = 0, o7 = 0;
    if (active) {
        const float* selfae = L ? g_selfae1 : g_selfae0;
        float pself = __expf(lrelu(g_als[n * 4 + hh] + g_ald[n * 4 + hh] + selfae[hh]));
        float a0 = 0, a1 = 0, a2 = 0, a3 = 0, a4 = 0, a5 = 0, a6 = 0, a7 = 0;
        {
            uint4 u = ((const uint4*)(g_hh + (size_t)n * 256))[lane];
            acc8(a0, a1, a2, a3, a4, a5, a6, a7, u, pself);
        }
        float denom = pself;
        int base = g_offs[n], deg = g_deg[n];
        for (int i0 = 0; i0 < deg; i0 += 32) {
            int cnt = min(32, deg - i0);
            int sl = 0;
            if (lane < cnt) sl = g_srcPerm[base + i0 + lane];
            int j = 0;
            for (; j + 8 <= cnt; j += 8) {
                int s0 = __shfl_sync(0xFFFFFFFFu, sl, j);
                int s1 = __shfl_sync(0xFFFFFFFFu, sl, j + 1);
                int s2 = __shfl_sync(0xFFFFFFFFu, sl, j + 2);
                int s3 = __shfl_sync(0xFFFFFFFFu, sl, j + 3);
                int s4 = __shfl_sync(0xFFFFFFFFu, sl, j + 4);
                int s5 = __shfl_sync(0xFFFFFFFFu, sl, j + 5);
                int s6 = __shfl_sync(0xFFFFFFFFu, sl, j + 6);
                int s7 = __shfl_sync(0xFFFFFFFFu, sl, j + 7);
                size_t pb = (size_t)(base + i0 + j) * 4 + hh;
                float p0 = g_p[pb], p1 = g_p[pb + 4], p2 = g_p[pb + 8], p3 = g_p[pb + 12];
                float p4 = g_p[pb + 16], p5 = g_p[pb + 20], p6 = g_p[pb + 24], p7 = g_p[pb + 28];
                uint4 u0 = ((const uint4*)(g_hh + (size_t)s0 * 256))[lane];
                uint4 u1 = ((const uint4*)(g_hh + (size_t)s1 * 256))[lane];
                uint4 u2 = ((const uint4*)(g_hh + (size_t)s2 * 256))[lane];
                uint4 u3 = ((const uint4*)(g_hh + (size_t)s3 * 256))[lane];
                uint4 u4 = ((const uint4*)(g_hh + (size_t)s4 * 256))[lane];
                uint4 u5 = ((const uint4*)(g_hh + (size_t)s5 * 256))[lane];
                uint4 u6 = ((const uint4*)(g_hh + (size_t)s6 * 256))[lane];
                uint4 u7 = ((const uint4*)(g_hh + (size_t)s7 * 256))[lane];
                acc8(a0, a1, a2, a3, a4, a5, a6, a7, u0, p0);
                acc8(a0, a1, a2, a3, a4, a5, a6, a7, u1, p1);
                acc8(a0, a1, a2, a3, a4, a5, a6, a7, u2, p2);
                acc8(a0, a1, a2, a3, a4, a5, a6, a7, u3, p3);
                acc8(a0, a1, a2, a3, a4, a5, a6, a7, u4, p4);
                acc8(a0, a1, a2, a3, a4, a5, a6, a7, u5, p5);
                acc8(a0, a1, a2, a3, a4, a5, a6, a7, u6, p6);
                acc8(a0, a1, a2, a3, a4, a5, a6, a7, u7, p7);
                denom += p0 + p1 + p2 + p3 + p4 + p5 + p6 + p7;
            }
            for (; j < cnt; j++) {
                int s0 = __shfl_sync(0xFFFFFFFFu, sl, j);
                float p0 = g_p[(size_t)(base + i0 + j) * 4 + hh];
                uint4 u0 = ((const uint4*)(g_hh + (size_t)s0 * 256))[lane];
                acc8(a0, a1, a2, a3, a4, a5, a6, a7, u0, p0);
                denom += p0;
            }
        }
        float inv = 1.f / (denom + 1e-16f);
        int c = lane * 8;
        o0 = a0 * inv + b[c + 0]; o1 = a1 * inv + b[c + 1];
        o2 = a2 * inv + b[c + 2]; o3 = a3 * inv + b[c + 3];
        o4 = a4 * inv + b[c + 4]; o5 = a5 * inv + b[c + 5];
        o6 = a6 * inv + b[c + 6]; o7 = a7 * inv + b[c + 7];
        if (L == 0) {
            o0 = fmaxf(o0, 0.f); o1 = fmaxf(o1, 0.f); o2 = fmaxf(o2, 0.f); o3 = fmaxf(o3, 0.f);
            o4 = fmaxf(o4, 0.f); o5 = fmaxf(o5, 0.f); o6 = fmaxf(o6, 0.f); o7 = fmaxf(o7, 0.f);
            __half2 q0 = __floats2half2_rn(o0, o1), q1 = __floats2half2_rn(o2, o3);
            __half2 q2 = __floats2half2_rn(o4, o5), q3 = __floats2half2_rn(o6, o7);
            uint4 pk;
            pk.x = *(unsigned*)&q0; pk.y = *(unsigned*)&q1;
            pk.z = *(unsigned*)&q2; pk.w = *(unsigned*)&q3;
            ((uint4*)(g_x1h + (size_t)n * 256))[lane] = pk;
        } else {
            float* op = g_x1 + (size_t)n * 256 + c;
            ((float4*)op)[0] = make_float4(o0, o1, o2, o3);
            ((float4*)op)[1] = make_float4(o4, o5, o6, o7);
        }
    }
    if (L == 1) {
        __shared__ float tile[8 * 256];
        if (active) {
            float* tp = tile + wib * 256 + lane * 8;
            ((float4*)tp)[0] = make_float4(o0, o1, o2, o3);
            ((float4*)tp)[1] = make_float4(o4, o5, o6, o7);
        }
        __syncthreads();
        int c = threadIdx.x;
        int nb = min(8, N - blockIdx.x * 8);
        float s = 0.f, m = -FLT_MAX;
        for (int w = 0; w < nb; w++) {
            float v = tile[w * 256 + c];
            s += v;
            m = fmaxf(m, v);
        }
        g_poolSum[(size_t)blockIdx.x * 256 + c] = s;
        g_poolMax[(size_t)blockIdx.x * 256 + c] = m;
    }
}

// ---------------- layer 1 node transform: tensor-core GEMM ----------------
#define A_STRIDE 264
__global__ __launch_bounds__(256) void k_node1mma(int N) {
    __shared__ __align__(16) __half As[64 * A_STRIDE];
    int tid = threadIdx.x;
    int warp = tid >> 5, lane = tid & 31;
    int m0 = blockIdx.x * 64;
    for (int idx = tid; idx < 64 * 32; idx += 256) {
        int r = idx >> 5, c = idx & 31;
        int nrow = m0 + r;
        uint4 v = make_uint4(0, 0, 0, 0);
        if (nrow < N) v = ((const uint4*)(g_x1h + (size_t)nrow * 256))[c];
        *(uint4*)&As[r * A_STRIDE + c * 8] = v;
    }
    __syncthreads();

    float acc[4][4][4];
#pragma unroll
    for (int mt = 0; mt < 4; mt++)
#pragma unroll
        for (int nt = 0; nt < 4; nt++)
#pragma unroll
            for (int r = 0; r < 4; r++) acc[mt][nt][r] = 0.f;

    int nbase = warp * 32;
    for (int k0 = 0; k0 < 256; k0 += 16) {
        unsigned aR[4][4];
        int arow = lane & 15;
        int acol = k0 + ((lane >> 4) << 3);
#pragma unroll
        for (int mt = 0; mt < 4; mt++) {
            unsigned saddr =
                (unsigned)__cvta_generic_to_shared(&As[(mt * 16 + arow) * A_STRIDE + acol]);
            asm volatile("ldmatrix.sync.aligned.m8n8.x4.shared.b16 {%0,%1,%2,%3}, [%4];"
                         : "=r"(aR[mt][0]), "=r"(aR[mt][1]), "=r"(aR[mt][2]), "=r"(aR[mt][3])
                         : "r"(saddr));
        }
#pragma unroll
        for (int nt = 0; nt < 4; nt++) {
            const __half* bp =
                g_W1h + (size_t)(nbase + nt * 8 + (lane >> 2)) * 256 + k0 + ((lane & 3) << 1);
            unsigned b0 = *(const unsigned*)bp;
            unsigned b1 = *(const unsigned*)(bp + 8);
#pragma unroll
            for (int mt = 0; mt < 4; mt++)
                mma16816(acc[mt][nt][0], acc[mt][nt][1], acc[mt][nt][2], acc[mt][nt][3],
                         aR[mt][0], aR[mt][1], aR[mt][2], aR[mt][3], b0, b1);
        }
    }
#pragma unroll
    for (int mt = 0; mt < 4; mt++) {
#pragma unroll
        for (int nt = 0; nt < 4; nt++) {
            int r0 = m0 + mt * 16 + (lane >> 2);
            int cc = nbase + nt * 8 + ((lane & 3) << 1);
            if (r0 < N) {
                __half2 v = __floats2half2_rn(acc[mt][nt][0], acc[mt][nt][1]);
                *(__half2*)&g_hh[(size_t)r0 * 256 + cc] = v;
            }
            int r1 = r0 + 8;
            if (r1 < N) {
                __half2 v = __floats2half2_rn(acc[mt][nt][2], acc[mt][nt][3]);
                *(__half2*)&g_hh[(size_t)r1 * 256 + cc] = v;
            }
        }
    }
}

// ---------------- layer-1 attention logits from h1 ----------------
__global__ __launch_bounds__(256) void k_logits1(const float* __restrict__ as1,
                                                 const float* __restrict__ ad1, int N) {
    __shared__ float sa[256], sd[256];
    sa[threadIdx.x] = as1[threadIdx.x];
    sd[threadIdx.x] = ad1[threadIdx.x];
    __syncthreads();
    int wib = threadIdx.x >> 5, lane = threadIdx.x & 31;
    int n = blockIdx.x * 8 + wib;
    if (n >= N) return;
    int hh = lane >> 3;
    int c = lane * 8;
    uint4 u = ((const uint4*)(g_hh + (size_t)n * 256))[lane];
    float2 f0 = __half22float2(*(const __half2*)&u.x);
    float2 f1 = __half22float2(*(const __half2*)&u.y);
    float2 f2 = __half22float2(*(const __half2*)&u.z);
    float2 f3 = __half22float2(*(const __half2*)&u.w);
    float s = f0.x * sa[c] + f0.y * sa[c + 1] + f1.x * sa[c + 2] + f1.y * sa[c + 3] +
              f2.x * sa[c + 4] + f2.y * sa[c + 5] + f3.x * sa[c + 6] + f3.y * sa[c + 7];
    float d = f0.x * sd[c] + f0.y * sd[c + 1] + f1.x * sd[c + 2] + f1.y * sd[c + 3] +
              f2.x * sd[c + 4] + f2.y * sd[c + 5] + f3.x * sd[c + 6] + f3.y * sd[c + 7];
#pragma unroll
    for (int o = 4; o > 0; o >>= 1) {
        s += __shfl_xor_sync(0xFFFFFFFFu, s, o);
        d += __shfl_xor_sync(0xFFFFFFFFu, d, o);
    }
    if ((lane & 7) == 0) {
        g_als[n * 4 + hh] = s;
        g_ald[n * 4 + hh] = d;
    }
}

// ---------------- pooling finalize + tail ----------------
__global__ void k_poolfin(int NB) {
    int c = threadIdx.x;
    float s = 0.f, m = -FLT_MAX;
    for (int i = blockIdx.x; i < NB; i += gridDim.x) {
        s += g_poolSum[(size_t)i * 256 + c];
        m = fmaxf(m, g_poolMax[(size_t)i * 256 + c]);
    }
    atomicAdd(&g_meansum[c], s);
    atomicMax(&g_maxbits[c], encf(m));
}

__global__ void k_fin(int N) {
    int c = threadIdx.x;
    g_meansum[c] /= (float)N;
}

__global__ void k_dot(int N) {
    int gw = (blockIdx.x * blockDim.x + threadIdx.x) >> 5;
    int lane = threadIdx.x & 31;
    if (gw >= N) return;
    float s = 0.f;
#pragma unroll
    for (int i = 0; i < 8; i++) {
        int c = lane + i * 32;
        s += g_x1[(size_t)gw * 256 + c] * g_meansum[c];
    }
#pragma unroll
    for (int o = 16; o > 0; o >>= 1) s += __shfl_down_sync(0xFFFFFFFFu, s, o);
    if (lane == 0) {
        g_s[gw] = s;
        atomicMax(&g_smaxbits, encf(s));
    }
}

__global__ void k_exp(int N) {
    __shared__ float sm[256];
    int i = blockIdx.x * blockDim.x + threadIdx.x;
    float smax = decf(g_smaxbits);
    float v = 0.f;
    if (i < N) {
        v = __expf(g_s[i] - smax);
        g_pn[i] = v;
    }
    sm[threadIdx.x] = v;
    __syncthreads();
    for (int s = 128; s > 0; s >>= 1) {
        if (threadIdx.x < s) sm[threadIdx.x] += sm[threadIdx.x + s];
        __syncthreads();
    }
    if (threadIdx.x == 0) atomicAdd(&g_Z, sm[0]);
}

__global__ void k_attpool(int N) {
    int c = threadIdx.x;
    int nb = blockIdx.x * 64;
    float s = 0.f;
    for (int j = 0; j < 64; j++) {
        int n = nb + j;
        if (n < N) s += g_x1[(size_t)n * 256 + c] * g_pn[n];
    }
    atomicAdd(&g_attsum[c], s);
}

__global__ void k_mlp(const float* __restrict__ Wm1, const float* __restrict__ bm1,
                      const float* __restrict__ Wm2, const float* __restrict__ bm2,
                      const float* __restrict__ Wm3, const float* __restrict__ bm3,
                      float* __restrict__ out) {
    __shared__ float comb[768], z1[128], z2[64];
    int tid = threadIdx.x;
    float Zinv = 1.f / g_Z;
    comb[tid] = g_meansum[tid];
    comb[256 + tid] = decf(g_maxbits[tid]);
    comb[512 + tid] = g_attsum[tid] * Zinv;
    __syncthreads();
    if (tid < 128) {
        float s = bm1[tid];
        for (int k = 0; k < 768; k++) s += comb[k] * Wm1[k * 128 + tid];
        z1[tid] = fmaxf(s, 0.f);
    }
    __syncthreads();
    if (tid < 64) {
        float s = bm2[tid];
        for (int k = 0; k < 128; k++) s += z1[k] * Wm2[k * 64 + tid];
        z2[tid] = fmaxf(s, 0.f);
    }
    __syncthreads();
    if (tid < 128) {
        float s = bm3[tid];
        for (int k = 0; k < 64; k++) s += z2[k] * Wm3[k * 128 + tid];
        out[tid] = s;
    }
}

// ---------------- launch ----------------
extern "C" void kernel_launch(void* const* d_in, const int* in_sizes, int n_in,
                              void* d_out, int out_size) {
    const float* x   = (const float*)d_in[0];
    const int*   ei  = (const int*)d_in[1];
    const float* ea  = (const float*)d_in[2];
    const float* W0  = (const float*)d_in[3];
    const float* as0 = (const float*)d_in[4];
    const float* ad0 = (const float*)d_in[5];
    const float* We0 = (const float*)d_in[6];
    const float* ae0 = (const float*)d_in[7];
    const float* b0  = (const float*)d_in[8];
    const float* W1  = (const float*)d_in[9];
    const float* as1 = (const float*)d_in[10];
    const float* ad1 = (const float*)d_in[11];
    const float* We1 = (const float*)d_in[12];
    const float* ae1 = (const float*)d_in[13];
    const float* b1  = (const float*)d_in[14];
    const float* Wm1 = (const float*)d_in[15];
    const float* bm1 = (const float*)d_in[16];
    const float* Wm2 = (const float*)d_in[17];
    const float* bm2 = (const float*)d_in[18];
    const float* Wm3 = (const float*)d_in[19];
    const float* bm3 = (const float*)d_in[20];

    int N = in_sizes[0] / 5;
    int E = in_sizes[1] / 2;
    const int* src = ei;
    const int* dst = ei + E;

    int NB = (N + 1023) / 1024;
    int EB = (E + 255) / 256;
    int GB = (N + 7) / 8;

    k_zero<<<(N + 255) / 256, 256>>>(N);
    k_meanEA<<<512, 256>>>(ea, E);
    k_deg<<<EB, 256>>>(dst, E);
    k_scanA<<<NB, 1024>>>(N);
    k_scanB<<<1, 64>>>(NB);
    k_scanC<<<NB, 1024>>>(N);
    k_place<<<EB, 256>>>(src, dst, E);
    k_pre<<<1, 256>>>(W0, as0, ad0, We0, ae0, We1, ae1, (float)E);
    k_w1h<<<256, 256>>>(W1);

    // layer 0 (x-space gather; h0 never materialized)
    k_node0b<<<(N * 8 + 255) / 256, 256>>>(x, N);
    k_edge<0><<<EB, 256>>>(src, dst, ea, E);
    k_gather0<<<GB, 256>>>(x, W0, b0, N);

    // layer 1 (unchanged from R7)
    k_node1mma<<<(N + 63) / 64, 256>>>(N);
    k_logits1<<<GB, 256>>>(as1, ad1, N);
    k_edge<1><<<EB, 256>>>(src, dst, ea, E);
    k_gather<1><<<GB, 256>>>(b1, N);

    // pooling + MLP
    k_poolfin<<<64, 256>>>(GB);
    k_fin<<<1, 256>>>(N);
    k_dot<<<(N * 32 + 255) / 256, 256>>>(N);
    k_exp<<<(N + 255) / 256, 256>>>(N);
    k_attpool<<<(N + 63) / 64, 256>>>(N);
    k_mlp<<<1, 256>>>(Wm1, bm1, Wm2, bm2, Wm3, bm3, (float*)d_out);
}

// round 15
// speedup vs baseline: 1.1346x; 1.1346x over previous
#include <cuda_runtime.h>
#include <cuda_fp16.h>
#include <cuda_bf16.h>
#include <cfloat>

#define N_MAX 50000
#define E_MAX 800000
#define PB_MAX ((N_MAX + 7) / 8)
#define LRELU 0.2f
#define ENC_NEGINF 0x007FFFFFu

// ---------------- device scratch ----------------
__device__ __half g_hh[N_MAX * 256];   // message features fp16 (gather consumer)
__device__ __half g_x1h[N_MAX * 256];  // layer-0 output fp16 (node1mma A operand)
__device__ __half g_W1h[256 * 256];    // W1 transposed (n-major), fp16
__device__ float g_x1[N_MAX * 256];    // final layer output (fp32, pooling consumers)
__device__ float g_als[N_MAX * 4];
__device__ float g_ald[N_MAX * 4];
__device__ float g_p[E_MAX * 4];       // attention weights fp32, CSR order
__device__ int   g_deg[N_MAX];
__device__ int   g_offs[N_MAX];
__device__ int   g_cursor[N_MAX];
__device__ int   g_srcPerm[E_MAX];
__device__ int   g_epos[E_MAX];
__device__ int   g_bsum[64];
__device__ float g_poolSum[PB_MAX * 256];
__device__ float g_poolMax[PB_MAX * 256];

__device__ float g_asEff0[5 * 4], g_adEff0[5 * 4], g_aeEff0[4 * 4], g_selfae0[4];
__device__ float g_aeEff1[4 * 4], g_selfae1[4];
__device__ float g_meanRaw[4];

__device__ float    g_meansum[256];   // UNNORMALIZED sum over nodes
__device__ unsigned g_maxbits[256];
__device__ float    g_attsum[256];
__device__ float    g_pn[N_MAX];
__device__ float    g_Z;

// ---------------- helpers ----------------
__device__ __forceinline__ unsigned encf(float f) {
    unsigned b = __float_as_uint(f);
    return (b & 0x80000000u) ? ~b : (b | 0x80000000u);
}
__device__ __forceinline__ float decf(unsigned u) {
    return (u & 0x80000000u) ? __uint_as_float(u ^ 0x80000000u) : __uint_as_float(~u);
}
__device__ __forceinline__ float lrelu(float a) { return a > 0.f ? a : LRELU * a; }

__device__ __forceinline__ void acc8(float& a0, float& a1, float& a2, float& a3,
                                     float& a4, float& a5, float& a6, float& a7,
                                     uint4 u, float p) {
    float2 f;
    f = __half22float2(*(const __half2*)&u.x); a0 += p * f.x; a1 += p * f.y;
    f = __half22float2(*(const __half2*)&u.y); a2 += p * f.x; a3 += p * f.y;
    f = __half22float2(*(const __half2*)&u.z); a4 += p * f.x; a5 += p * f.y;
    f = __half22float2(*(const __half2*)&u.w); a6 += p * f.x; a7 += p * f.y;
}

__device__ __forceinline__ void mma16816(float& c0, float& c1, float& c2, float& c3,
                                         unsigned a0, unsigned a1, unsigned a2, unsigned a3,
                                         unsigned b0, unsigned b1) {
    asm volatile(
        "mma.sync.aligned.m16n8k16.row.col.f32.f16.f16.f32 "
        "{%0,%1,%2,%3}, {%4,%5,%6,%7}, {%8,%9}, {%0,%1,%2,%3};"
        : "+f"(c0), "+f"(c1), "+f"(c2), "+f"(c3)
        : "r"(a0), "r"(a1), "r"(a2), "r"(a3), "r"(b0), "r"(b1));
}

// ---------------- setup kernels ----------------
__global__ void k_zero(int N) {
    int i = blockIdx.x * blockDim.x + threadIdx.x;
    if (i < N) { g_deg[i] = 0; g_cursor[i] = 0; }
    if (i < 256) { g_meansum[i] = 0.f; g_attsum[i] = 0.f; g_maxbits[i] = ENC_NEGINF; }
    if (i < 4) g_meanRaw[i] = 0.f;
    if (i == 0) g_Z = 0.f;
}

// one edge pass: edge_attr mean partials + degree histogram
__global__ void k_meanEA_deg(const float* __restrict__ ea, const int* __restrict__ dst, int E) {
    __shared__ float sm[256][4];
    float a0 = 0, a1 = 0, a2 = 0, a3 = 0;
    int stride = gridDim.x * blockDim.x;
    for (int e = blockIdx.x * blockDim.x + threadIdx.x; e < E; e += stride) {
        float4 v = ((const float4*)ea)[e];
        a0 += v.x; a1 += v.y; a2 += v.z; a3 += v.w;
        atomicAdd(&g_deg[dst[e]], 1);
    }
    sm[threadIdx.x][0] = a0; sm[threadIdx.x][1] = a1;
    sm[threadIdx.x][2] = a2; sm[threadIdx.x][3] = a3;
    __syncthreads();
    for (int s = 128; s > 0; s >>= 1) {
        if (threadIdx.x < s) {
            sm[threadIdx.x][0] += sm[threadIdx.x + s][0];
            sm[threadIdx.x][1] += sm[threadIdx.x + s][1];
            sm[threadIdx.x][2] += sm[threadIdx.x + s][2];
            sm[threadIdx.x][3] += sm[threadIdx.x + s][3];
        }
        __syncthreads();
    }
    if (threadIdx.x < 4) atomicAdd(&g_meanRaw[threadIdx.x], sm[0][threadIdx.x]);
}

__global__ void k_scanA(int N) {
    __shared__ int sm[1024];
    int i = blockIdx.x * 1024 + threadIdx.x;
    int v = (i < N) ? g_deg[i] : 0;
    sm[threadIdx.x] = v;
    __syncthreads();
    for (int d = 1; d < 1024; d <<= 1) {
        int t = (threadIdx.x >= d) ? sm[threadIdx.x - d] : 0;
        __syncthreads();
        sm[threadIdx.x] += t;
        __syncthreads();
    }
    if (i < N) g_offs[i] = sm[threadIdx.x] - v;
    if (threadIdx.x == 1023) g_bsum[blockIdx.x] = sm[1023];
}

// merged scanB+scanC: every block recomputes the trivial 64-entry exclusive
// scan of block sums in smem, then offsets its own tile of g_offs.
__global__ void k_scanBC(int NB, int N) {
    __shared__ int sm[64];
    int t = threadIdx.x;
    if (t < 64) sm[t] = (t < NB) ? g_bsum[t] : 0;
    __syncthreads();
    if (t == 0) {
        int run = 0;
        for (int j = 0; j < 64; j++) { int tmp = sm[j]; sm[j] = run; run += tmp; }
    }
    __syncthreads();
    int i = blockIdx.x * 1024 + t;
    if (i < N) g_offs[i] += sm[blockIdx.x];
}

__global__ void k_place(const int* __restrict__ src, const int* __restrict__ dst, int E) {
    int e = blockIdx.x * blockDim.x + threadIdx.x;
    if (e < E) {
        int d = dst[e];
        int pos = g_offs[d] + atomicAdd(&g_cursor[d], 1);
        g_epos[e] = pos;
        g_srcPerm[pos] = src[e];
    }
}

__global__ void k_w1h(const float* __restrict__ W1) {
    int idx = blockIdx.x * 256 + threadIdx.x;
    int k = idx >> 8, n = idx & 255;
    g_W1h[n * 256 + k] = __float2half_rn(W1[k * 256 + n]);
}

__global__ void k_pre(const float* __restrict__ W0, const float* __restrict__ as0,
                      const float* __restrict__ ad0, const float* __restrict__ We0,
                      const float* __restrict__ ae0,
                      const float* __restrict__ We1, const float* __restrict__ ae1,
                      float Ef) {
    __shared__ float sm_mean[4];
    int tid = threadIdx.x;
    for (int idx = tid; idx < 20; idx += 256) {
        int k = idx >> 2, h = idx & 3;
        float s1 = 0, s2 = 0;
        for (int c = 0; c < 64; c++) {
            float w = W0[k * 256 + h * 64 + c];
            s1 += w * as0[h * 64 + c]; s2 += w * ad0[h * 64 + c];
        }
        g_asEff0[idx] = s1; g_adEff0[idx] = s2;
    }
    for (int idx = tid; idx < 16; idx += 256) {
        int k = idx >> 2, h = idx & 3;
        float s0 = 0, s1 = 0;
        for (int c = 0; c < 64; c++) {
            s0 += We0[k * 256 + h * 64 + c] * ae0[h * 64 + c];
            s1 += We1[k * 256 + h * 64 + c] * ae1[h * 64 + c];
        }
        g_aeEff0[idx] = s0; g_aeEff1[idx] = s1;
    }
    __syncthreads();
    if (tid < 4) sm_mean[tid] = g_meanRaw[tid] / Ef;
    __syncthreads();
    if (tid < 4) {
        float s0 = 0, s1 = 0;
        for (int k = 0; k < 4; k++) {
            s0 += sm_mean[k] * g_aeEff0[k * 4 + tid];
            s1 += sm_mean[k] * g_aeEff1[k * 4 + tid];
        }
        g_selfae0[tid] = s0; g_selfae1[tid] = s1;
    }
}

// ---------------- layer 0 node transform (h fp16) — FROZEN (R7) ----------------
__global__ void k_node0(const float* __restrict__ x, const float* __restrict__ W0, int N) {
    int n = blockIdx.x;
    if (n >= N) return;
    int tid = threadIdx.x;
    float xk[5];
#pragma unroll
    for (int k = 0; k < 5; k++) xk[k] = x[n * 5 + k];
    float s = 0.f;
#pragma unroll
    for (int k = 0; k < 5; k++) s += xk[k] * W0[k * 256 + tid];
    g_hh[(size_t)n * 256 + tid] = __float2half_rn(s);
    if (tid < 8) {
        int which = tid >> 2, h = tid & 3;
        const float* eff = which ? g_adEff0 : g_asEff0;
        float a = 0.f;
#pragma unroll
        for (int k = 0; k < 5; k++) a += xk[k] * eff[k * 4 + h];
        (which ? g_ald : g_als)[n * 4 + h] = a;
    }
}

// ---------------- per-edge attention weights — FROZEN (R7) ----------------
template <int L>
__global__ void k_edge(const int* __restrict__ src, const int* __restrict__ dst,
                       const float* __restrict__ ea, int E) {
    int e = blockIdx.x * blockDim.x + threadIdx.x;
    if (e >= E) return;
    const float* aeEff = L ? g_aeEff1 : g_aeEff0;
    float4 v = ((const float4*)ea)[e];
    int s = src[e], d = dst[e];
    float4 as = ((const float4*)g_als)[s];
    float4 ad = ((const float4*)g_ald)[d];
    float4 p;
    float ale;
    ale = v.x * aeEff[0] + v.y * aeEff[4] + v.z * aeEff[8] + v.w * aeEff[12];
    p.x = __expf(lrelu(as.x + ad.x + ale));
    ale = v.x * aeEff[1] + v.y * aeEff[5] + v.z * aeEff[9] + v.w * aeEff[13];
    p.y = __expf(lrelu(as.y + ad.y + ale));
    ale = v.x * aeEff[2] + v.y * aeEff[6] + v.z * aeEff[10] + v.w * aeEff[14];
    p.z = __expf(lrelu(as.z + ad.z + ale));
    ale = v.x * aeEff[3] + v.y * aeEff[7] + v.z * aeEff[11] + v.w * aeEff[15];
    p.w = __expf(lrelu(as.w + ad.w + ale));
    ((float4*)g_p)[g_epos[e]] = p;
}

// ---------------- gather — FROZEN (R7) ----------------
template <int L>
__global__ __launch_bounds__(256) void k_gather(const float* __restrict__ b, int N) {
    int wib = threadIdx.x >> 5;
    int lane = threadIdx.x & 31;
    int n = blockIdx.x * 8 + wib;
    int hh = lane >> 3;
    bool active = (n < N);
    float o0 = 0, o1 = 0, o2 = 0, o3 = 0, o4 = 0, o5 = 0, o6 = 0, o7 = 0;
    if (active) {
        const float* selfae = L ? g_selfae1 : g_selfae0;
        float pself = __expf(lrelu(g_als[n * 4 + hh] + g_ald[n * 4 + hh] + selfae[hh]));
        float a0 = 0, a1 = 0, a2 = 0, a3 = 0, a4 = 0, a5 = 0, a6 = 0, a7 = 0;
        {
            uint4 u = ((const uint4*)(g_hh + (size_t)n * 256))[lane];
            acc8(a0, a1, a2, a3, a4, a5, a6, a7, u, pself);
        }
        float denom = pself;
        int base = g_offs[n], deg = g_deg[n];
        for (int i0 = 0; i0 < deg; i0 += 32) {
            int cnt = min(32, deg - i0);
            int sl = 0;
            if (lane < cnt) sl = g_srcPerm[base + i0 + lane];
            int j = 0;
            for (; j + 8 <= cnt; j += 8) {
                int s0 = __shfl_sync(0xFFFFFFFFu, sl, j);
                int s1 = __shfl_sync(0xFFFFFFFFu, sl, j + 1);
                int s2 = __shfl_sync(0xFFFFFFFFu, sl, j + 2);
                int s3 = __shfl_sync(0xFFFFFFFFu, sl, j + 3);
                int s4 = __shfl_sync(0xFFFFFFFFu, sl, j + 4);
                int s5 = __shfl_sync(0xFFFFFFFFu, sl, j + 5);
                int s6 = __shfl_sync(0xFFFFFFFFu, sl, j + 6);
                int s7 = __shfl_sync(0xFFFFFFFFu, sl, j + 7);
                size_t pb = (size_t)(base + i0 + j) * 4 + hh;
                float p0 = g_p[pb], p1 = g_p[pb + 4], p2 = g_p[pb + 8], p3 = g_p[pb + 12];
                float p4 = g_p[pb + 16], p5 = g_p[pb + 20], p6 = g_p[pb + 24], p7 = g_p[pb + 28];
                uint4 u0 = ((const uint4*)(g_hh + (size_t)s0 * 256))[lane];
                uint4 u1 = ((const uint4*)(g_hh + (size_t)s1 * 256))[lane];
                uint4 u2 = ((const uint4*)(g_hh + (size_t)s2 * 256))[lane];
                uint4 u3 = ((const uint4*)(g_hh + (size_t)s3 * 256))[lane];
                uint4 u4 = ((const uint4*)(g_hh + (size_t)s4 * 256))[lane];
                uint4 u5 = ((const uint4*)(g_hh + (size_t)s5 * 256))[lane];
                uint4 u6 = ((const uint4*)(g_hh + (size_t)s6 * 256))[lane];
                uint4 u7 = ((const uint4*)(g_hh + (size_t)s7 * 256))[lane];
                acc8(a0, a1, a2, a3, a4, a5, a6, a7, u0, p0);
                acc8(a0, a1, a2, a3, a4, a5, a6, a7, u1, p1);
                acc8(a0, a1, a2, a3, a4, a5, a6, a7, u2, p2);
                acc8(a0, a1, a2, a3, a4, a5, a6, a7, u3, p3);
                acc8(a0, a1, a2, a3, a4, a5, a6, a7, u4, p4);
                acc8(a0, a1, a2, a3, a4, a5, a6, a7, u5, p5);
                acc8(a0, a1, a2, a3, a4, a5, a6, a7, u6, p6);
                acc8(a0, a1, a2, a3, a4, a5, a6, a7, u7, p7);
                denom += p0 + p1 + p2 + p3 + p4 + p5 + p6 + p7;
            }
            for (; j < cnt; j++) {
                int s0 = __shfl_sync(0xFFFFFFFFu, sl, j);
                float p0 = g_p[(size_t)(base + i0 + j) * 4 + hh];
                uint4 u0 = ((const uint4*)(g_hh + (size_t)s0 * 256))[lane];
                acc8(a0, a1, a2, a3, a4, a5, a6, a7, u0, p0);
                denom += p0;
            }
        }
        float inv = 1.f / (denom + 1e-16f);
        int c = lane * 8;
        o0 = a0 * inv + b[c + 0]; o1 = a1 * inv + b[c + 1];
        o2 = a2 * inv + b[c + 2]; o3 = a3 * inv + b[c + 3];
        o4 = a4 * inv + b[c + 4]; o5 = a5 * inv + b[c + 5];
        o6 = a6 * inv + b[c + 6]; o7 = a7 * inv + b[c + 7];
        if (L == 0) {
            o0 = fmaxf(o0, 0.f); o1 = fmaxf(o1, 0.f); o2 = fmaxf(o2, 0.f); o3 = fmaxf(o3, 0.f);
            o4 = fmaxf(o4, 0.f); o5 = fmaxf(o5, 0.f); o6 = fmaxf(o6, 0.f); o7 = fmaxf(o7, 0.f);
            __half2 q0 = __floats2half2_rn(o0, o1), q1 = __floats2half2_rn(o2, o3);
            __half2 q2 = __floats2half2_rn(o4, o5), q3 = __floats2half2_rn(o6, o7);
            uint4 pk;
            pk.x = *(unsigned*)&q0; pk.y = *(unsigned*)&q1;
            pk.z = *(unsigned*)&q2; pk.w = *(unsigned*)&q3;
            ((uint4*)(g_x1h + (size_t)n * 256))[lane] = pk;
        } else {
            float* op = g_x1 + (size_t)n * 256 + c;
            ((float4*)op)[0] = make_float4(o0, o1, o2, o3);
            ((float4*)op)[1] = make_float4(o4, o5, o6, o7);
        }
    }
    if (L == 1) {
        __shared__ float tile[8 * 256];
        if (active) {
            float* tp = tile + wib * 256 + lane * 8;
            ((float4*)tp)[0] = make_float4(o0, o1, o2, o3);
            ((float4*)tp)[1] = make_float4(o4, o5, o6, o7);
        }
        __syncthreads();
        int c = threadIdx.x;
        int nb = min(8, N - blockIdx.x * 8);
        float s = 0.f, m = -FLT_MAX;
        for (int w = 0; w < nb; w++) {
            float v = tile[w * 256 + c];
            s += v;
            m = fmaxf(m, v);
        }
        g_poolSum[(size_t)blockIdx.x * 256 + c] = s;
        g_poolMax[(size_t)blockIdx.x * 256 + c] = m;
    }
}

// ---------------- layer 1 node transform: tensor-core GEMM — FROZEN (R7) ----------------
#define A_STRIDE 264
__global__ __launch_bounds__(256) void k_node1mma(int N) {
    __shared__ __align__(16) __half As[64 * A_STRIDE];
    int tid = threadIdx.x;
    int warp = tid >> 5, lane = tid & 31;
    int m0 = blockIdx.x * 64;
    for (int idx = tid; idx < 64 * 32; idx += 256) {
        int r = idx >> 5, c = idx & 31;
        int nrow = m0 + r;
        uint4 v = make_uint4(0, 0, 0, 0);
        if (nrow < N) v = ((const uint4*)(g_x1h + (size_t)nrow * 256))[c];
        *(uint4*)&As[r * A_STRIDE + c * 8] = v;
    }
    __syncthreads();

    float acc[4][4][4];
#pragma unroll
    for (int mt = 0; mt < 4; mt++)
#pragma unroll
        for (int nt = 0; nt < 4; nt++)
#pragma unroll
            for (int r = 0; r < 4; r++) acc[mt][nt][r] = 0.f;

    int nbase = warp * 32;
    for (int k0 = 0; k0 < 256; k0 += 16) {
        unsigned aR[4][4];
        int arow = lane & 15;
        int acol = k0 + ((lane >> 4) << 3);
#pragma unroll
        for (int mt = 0; mt < 4; mt++) {
            unsigned saddr =
                (unsigned)__cvta_generic_to_shared(&As[(mt * 16 + arow) * A_STRIDE + acol]);
            asm volatile("ldmatrix.sync.aligned.m8n8.x4.shared.b16 {%0,%1,%2,%3}, [%4];"
                         : "=r"(aR[mt][0]), "=r"(aR[mt][1]), "=r"(aR[mt][2]), "=r"(aR[mt][3])
                         : "r"(saddr));
        }
#pragma unroll
        for (int nt = 0; nt < 4; nt++) {
            const __half* bp =
                g_W1h + (size_t)(nbase + nt * 8 + (lane >> 2)) * 256 + k0 + ((lane & 3) << 1);
            unsigned b0 = *(const unsigned*)bp;
            unsigned b1 = *(const unsigned*)(bp + 8);
#pragma unroll
            for (int mt = 0; mt < 4; mt++)
                mma16816(acc[mt][nt][0], acc[mt][nt][1], acc[mt][nt][2], acc[mt][nt][3],
                         aR[mt][0], aR[mt][1], aR[mt][2], aR[mt][3], b0, b1);
        }
    }
#pragma unroll
    for (int mt = 0; mt < 4; mt++) {
#pragma unroll
        for (int nt = 0; nt < 4; nt++) {
            int r0 = m0 + mt * 16 + (lane >> 2);
            int cc = nbase + nt * 8 + ((lane & 3) << 1);
            if (r0 < N) {
                __half2 v = __floats2half2_rn(acc[mt][nt][0], acc[mt][nt][1]);
                *(__half2*)&g_hh[(size_t)r0 * 256 + cc] = v;
            }
            int r1 = r0 + 8;
            if (r1 < N) {
                __half2 v = __floats2half2_rn(acc[mt][nt][2], acc[mt][nt][3]);
                *(__half2*)&g_hh[(size_t)r1 * 256 + cc] = v;
            }
        }
    }
}

// ---------------- layer-1 attention logits from h1 — FROZEN (R7) ----------------
__global__ __launch_bounds__(256) void k_logits1(const float* __restrict__ as1,
                                                 const float* __restrict__ ad1, int N) {
    __shared__ float sa[256], sd[256];
    sa[threadIdx.x] = as1[threadIdx.x];
    sd[threadIdx.x] = ad1[threadIdx.x];
    __syncthreads();
    int wib = threadIdx.x >> 5, lane = threadIdx.x & 31;
    int n = blockIdx.x * 8 + wib;
    if (n >= N) return;
    int hh = lane >> 3;
    int c = lane * 8;
    uint4 u = ((const uint4*)(g_hh + (size_t)n * 256))[lane];
    float2 f0 = __half22float2(*(const __half2*)&u.x);
    float2 f1 = __half22float2(*(const __half2*)&u.y);
    float2 f2 = __half22float2(*(const __half2*)&u.z);
    float2 f3 = __half22float2(*(const __half2*)&u.w);
    float s = f0.x * sa[c] + f0.y * sa[c + 1] + f1.x * sa[c + 2] + f1.y * sa[c + 3] +
              f2.x * sa[c + 4] + f2.y * sa[c + 5] + f3.x * sa[c + 6] + f3.y * sa[c + 7];
    float d = f0.x * sd[c] + f0.y * sd[c + 1] + f1.x * sd[c + 2] + f1.y * sd[c + 3] +
              f2.x * sd[c + 4] + f2.y * sd[c + 5] + f3.x * sd[c + 6] + f3.y * sd[c + 7];
#pragma unroll
    for (int o = 4; o > 0; o >>= 1) {
        s += __shfl_xor_sync(0xFFFFFFFFu, s, o);
        d += __shfl_xor_sync(0xFFFFFFFFu, d, o);
    }
    if ((lane & 7) == 0) {
        g_als[n * 4 + hh] = s;
        g_ald[n * 4 + hh] = d;
    }
}

// ---------------- pooling finalize + tail ----------------
__global__ void k_poolfin(int NB) {
    int c = threadIdx.x;
    float s = 0.f, m = -FLT_MAX;
    for (int i = blockIdx.x; i < NB; i += gridDim.x) {
        s += g_poolSum[(size_t)i * 256 + c];
        m = fmaxf(m, g_poolMax[(size_t)i * 256 + c]);
    }
    atomicAdd(&g_meansum[c], s);
    atomicMax(&g_maxbits[c], encf(m));
}

// fused: s = (h . meansum)/N ; pn = exp(s) ; Z += pn  (no-max softmax, exact)
__global__ __launch_bounds__(256) void k_dotexp(int N) {
    __shared__ float wsum[8];
    int gw = (blockIdx.x * blockDim.x + threadIdx.x) >> 5;
    int lane = threadIdx.x & 31;
    float invN = 1.f / (float)N;
    float contrib = 0.f;
    if (gw < N) {
        float s = 0.f;
#pragma unroll
        for (int i = 0; i < 8; i++) {
            int c = lane + i * 32;
            s += g_x1[(size_t)gw * 256 + c] * g_meansum[c];
        }
#pragma unroll
        for (int o = 16; o > 0; o >>= 1) s += __shfl_down_sync(0xFFFFFFFFu, s, o);
        if (lane == 0) {
            float e = __expf(s * invN);
            g_pn[gw] = e;
            contrib = e;
        }
    }
    if (lane == 0) wsum[threadIdx.x >> 5] = contrib;
    __syncthreads();
    if (threadIdx.x < 8) {
        float v = wsum[threadIdx.x];
#pragma unroll
        for (int o = 4; o > 0; o >>= 1) v += __shfl_down_sync(0xFFu, v, o);
        if (threadIdx.x == 0) atomicAdd(&g_Z, v);
    }
}

__global__ void k_attpool(int N) {
    int c = threadIdx.x;
    int nb = blockIdx.x * 64;
    float s = 0.f;
    for (int j = 0; j < 64; j++) {
        int n = nb + j;
        if (n < N) s += g_x1[(size_t)n * 256 + c] * g_pn[n];
    }
    atomicAdd(&g_attsum[c], s);
}

__global__ void k_mlp(const float* __restrict__ Wm1, const float* __restrict__ bm1,
                      const float* __restrict__ Wm2, const float* __restrict__ bm2,
                      const float* __restrict__ Wm3, const float* __restrict__ bm3,
                      float* __restrict__ out, int N) {
    __shared__ float comb[768], z1[128], z2[64];
    int tid = threadIdx.x;
    float Zinv = 1.f / g_Z;
    comb[tid] = g_meansum[tid] / (float)N;
    comb[256 + tid] = decf(g_maxbits[tid]);
    comb[512 + tid] = g_attsum[tid] * Zinv;
    __syncthreads();
    if (tid < 128) {
        float s = bm1[tid];
        for (int k = 0; k < 768; k++) s += comb[k] * Wm1[k * 128 + tid];
        z1[tid] = fmaxf(s, 0.f);
    }
    __syncthreads();
    if (tid < 64) {
        float s = bm2[tid];
        for (int k = 0; k < 128; k++) s += z1[k] * Wm2[k * 64 + tid];
        z2[tid] = fmaxf(s, 0.f);
    }
    __syncthreads();
    if (tid < 128) {
        float s = bm3[tid];
        for (int k = 0; k < 64; k++) s += z2[k] * Wm3[k * 128 + tid];
        out[tid] = s;
    }
}

// ---------------- launch ----------------
extern "C" void kernel_launch(void* const* d_in, const int* in_sizes, int n_in,
                              void* d_out, int out_size) {
    const float* x   = (const float*)d_in[0];
    const int*   ei  = (const int*)d_in[1];
    const float* ea  = (const float*)d_in[2];
    const float* W0  = (const float*)d_in[3];
    const float* as0 = (const float*)d_in[4];
    const float* ad0 = (const float*)d_in[5];
    const float* We0 = (const float*)d_in[6];
    const float* ae0 = (const float*)d_in[7];
    const float* b0  = (const float*)d_in[8];
    const float* W1  = (const float*)d_in[9];
    const float* as1 = (const float*)d_in[10];
    const float* ad1 = (const float*)d_in[11];
    const float* We1 = (const float*)d_in[12];
    const float* ae1 = (const float*)d_in[13];
    const float* b1  = (const float*)d_in[14];
    const float* Wm1 = (const float*)d_in[15];
    const float* bm1 = (const float*)d_in[16];
    const float* Wm2 = (const float*)d_in[17];
    const float* bm2 = (const float*)d_in[18];
    const float* Wm3 = (const float*)d_in[19];
    const float* bm3 = (const float*)d_in[20];

    int N = in_sizes[0] / 5;
    int E = in_sizes[1] / 2;
    const int* src = ei;
    const int* dst = ei + E;

    int NB = (N + 1023) / 1024;
    int EB = (E + 255) / 256;
    int GB = (N + 7) / 8;

    k_zero<<<(N + 255) / 256, 256>>>(N);
    k_meanEA_deg<<<512, 256>>>(ea, dst, E);
    k_scanA<<<NB, 1024>>>(N);
    k_scanBC<<<NB, 1024>>>(NB, N);
    k_place<<<EB, 256>>>(src, dst, E);
    k_pre<<<1, 256>>>(W0, as0, ad0, We0, ae0, We1, ae1, (float)E);
    k_w1h<<<256, 256>>>(W1);

    // layer 0
    k_node0<<<N, 256>>>(x, W0, N);
    k_edge<0><<<EB, 256>>>(src, dst, ea, E);
    k_gather<0><<<GB, 256>>>(b0, N);

    // layer 1
    k_node1mma<<<(N + 63) / 64, 256>>>(N);
    k_logits1<<<GB, 256>>>(as1, ad1, N);
    k_edge<1><<<EB, 256>>>(src, dst, ea, E);
    k_gather<1><<<GB, 256>>>(b1, N);

    // pooling + MLP
    k_poolfin<<<64, 256>>>(GB);
    k_dotexp<<<(N * 32 + 255) / 256, 256>>>(N);
    k_attpool<<<(N + 63) / 64, 256>>>(N);
    k_mlp<<<1, 256>>>(Wm1, bm1, Wm2, bm2, Wm3, bm3, (float*)d_out, N);
}

// round 16
// speedup vs baseline: 1.1460x; 1.0101x over previous
#include <cuda_runtime.h>
#include <cuda_fp16.h>
#include <cuda_bf16.h>
#include <cfloat>

#define N_MAX 50000
#define E_MAX 800000
#define PB_MAX ((N_MAX + 7) / 8)
#define LRELU 0.2f
#define ENC_NEGINF 0x007FFFFFu

// ---------------- device scratch ----------------
__device__ __half g_hh[N_MAX * 256];   // message features fp16 (gather consumer)
__device__ __half g_x1h[N_MAX * 256];  // layer-0 output fp16 (node1mma A operand)
__device__ __half g_W1h[256 * 256];    // W1 transposed (n-major), fp16
__device__ float g_x1[N_MAX * 256];    // final layer output (fp32, pooling consumers)
__device__ float g_als[N_MAX * 4];
__device__ float g_ald[N_MAX * 4];
__device__ float g_p[E_MAX * 4];       // attention weights fp32, CSR order
__device__ int   g_deg[N_MAX];
__device__ int   g_offs[N_MAX];
__device__ int   g_cursor[N_MAX];
__device__ int   g_srcPerm[E_MAX];
__device__ int   g_epos[E_MAX];
__device__ int   g_bsum[64];
__device__ float g_poolSum[PB_MAX * 256];
__device__ float g_poolMax[PB_MAX * 256];

__device__ float g_asEff0[5 * 4], g_adEff0[5 * 4], g_aeEff0[4 * 4], g_selfae0[4];
__device__ float g_aeEff1[4 * 4], g_selfae1[4];
__device__ float g_meanRaw[4];

__device__ float    g_meansum[256];   // UNNORMALIZED sum over nodes
__device__ unsigned g_maxbits[256];
__device__ float    g_attsum[256];
__device__ float    g_pn[N_MAX];
__device__ float    g_Z;

// ---------------- helpers ----------------
__device__ __forceinline__ unsigned encf(float f) {
    unsigned b = __float_as_uint(f);
    return (b & 0x80000000u) ? ~b : (b | 0x80000000u);
}
__device__ __forceinline__ float decf(unsigned u) {
    return (u & 0x80000000u) ? __uint_as_float(u ^ 0x80000000u) : __uint_as_float(~u);
}
__device__ __forceinline__ float lrelu(float a) { return a > 0.f ? a : LRELU * a; }

__device__ __forceinline__ void acc8(float& a0, float& a1, float& a2, float& a3,
                                     float& a4, float& a5, float& a6, float& a7,
                                     uint4 u, float p) {
    float2 f;
    f = __half22float2(*(const __half2*)&u.x); a0 += p * f.x; a1 += p * f.y;
    f = __half22float2(*(const __half2*)&u.y); a2 += p * f.x; a3 += p * f.y;
    f = __half22float2(*(const __half2*)&u.z); a4 += p * f.x; a5 += p * f.y;
    f = __half22float2(*(const __half2*)&u.w); a6 += p * f.x; a7 += p * f.y;
}

__device__ __forceinline__ void mma16816(float& c0, float& c1, float& c2, float& c3,
                                         unsigned a0, unsigned a1, unsigned a2, unsigned a3,
                                         unsigned b0, unsigned b1) {
    asm volatile(
        "mma.sync.aligned.m16n8k16.row.col.f32.f16.f16.f32 "
        "{%0,%1,%2,%3}, {%4,%5,%6,%7}, {%8,%9}, {%0,%1,%2,%3};"
        : "+f"(c0), "+f"(c1), "+f"(c2), "+f"(c3)
        : "r"(a0), "r"(a1), "r"(a2), "r"(a3), "r"(b0), "r"(b1));
}

// ---------------- setup kernels ----------------
__global__ void k_zero(int N) {
    int i = blockIdx.x * blockDim.x + threadIdx.x;
    if (i < N) { g_deg[i] = 0; g_cursor[i] = 0; }
    if (i < 256) { g_meansum[i] = 0.f; g_attsum[i] = 0.f; g_maxbits[i] = ENC_NEGINF; }
    if (i < 4) g_meanRaw[i] = 0.f;
    if (i == 0) g_Z = 0.f;
}

// one edge pass: edge_attr mean partials + degree histogram
__global__ void k_meanEA_deg(const float* __restrict__ ea, const int* __restrict__ dst, int E) {
    __shared__ float sm[256][4];
    float a0 = 0, a1 = 0, a2 = 0, a3 = 0;
    int stride = gridDim.x * blockDim.x;
    for (int e = blockIdx.x * blockDim.x + threadIdx.x; e < E; e += stride) {
        float4 v = ((const float4*)ea)[e];
        a0 += v.x; a1 += v.y; a2 += v.z; a3 += v.w;
        atomicAdd(&g_deg[dst[e]], 1);
    }
    sm[threadIdx.x][0] = a0; sm[threadIdx.x][1] = a1;
    sm[threadIdx.x][2] = a2; sm[threadIdx.x][3] = a3;
    __syncthreads();
    for (int s = 128; s > 0; s >>= 1) {
        if (threadIdx.x < s) {
            sm[threadIdx.x][0] += sm[threadIdx.x + s][0];
            sm[threadIdx.x][1] += sm[threadIdx.x + s][1];
            sm[threadIdx.x][2] += sm[threadIdx.x + s][2];
            sm[threadIdx.x][3] += sm[threadIdx.x + s][3];
        }
        __syncthreads();
    }
    if (threadIdx.x < 4) atomicAdd(&g_meanRaw[threadIdx.x], sm[0][threadIdx.x]);
}

__global__ void k_scanA(int N) {
    __shared__ int sm[1024];
    int i = blockIdx.x * 1024 + threadIdx.x;
    int v = (i < N) ? g_deg[i] : 0;
    sm[threadIdx.x] = v;
    __syncthreads();
    for (int d = 1; d < 1024; d <<= 1) {
        int t = (threadIdx.x >= d) ? sm[threadIdx.x - d] : 0;
        __syncthreads();
        sm[threadIdx.x] += t;
        __syncthreads();
    }
    if (i < N) g_offs[i] = sm[threadIdx.x] - v;
    if (threadIdx.x == 1023) g_bsum[blockIdx.x] = sm[1023];
}

// merged scanB+scanC
__global__ void k_scanBC(int NB, int N) {
    __shared__ int sm[64];
    int t = threadIdx.x;
    if (t < 64) sm[t] = (t < NB) ? g_bsum[t] : 0;
    __syncthreads();
    if (t == 0) {
        int run = 0;
        for (int j = 0; j < 64; j++) { int tmp = sm[j]; sm[j] = run; run += tmp; }
    }
    __syncthreads();
    int i = blockIdx.x * 1024 + t;
    if (i < N) g_offs[i] += sm[blockIdx.x];
}

// merged k_pre + k_w1h: blocks 0..255 transpose W1 to fp16; block 256 runs precompute
__global__ void k_prew(const float* __restrict__ W1,
                       const float* __restrict__ W0, const float* __restrict__ as0,
                       const float* __restrict__ ad0, const float* __restrict__ We0,
                       const float* __restrict__ ae0,
                       const float* __restrict__ We1, const float* __restrict__ ae1,
                       float Ef) {
    if (blockIdx.x < 256) {
        int idx = blockIdx.x * 256 + threadIdx.x;
        int k = idx >> 8, n = idx & 255;
        g_W1h[n * 256 + k] = __float2half_rn(W1[k * 256 + n]);
        return;
    }
    __shared__ float sm_mean[4];
    int tid = threadIdx.x;
    for (int idx = tid; idx < 20; idx += 256) {
        int k = idx >> 2, h = idx & 3;
        float s1 = 0, s2 = 0;
        for (int c = 0; c < 64; c++) {
            float w = W0[k * 256 + h * 64 + c];
            s1 += w * as0[h * 64 + c]; s2 += w * ad0[h * 64 + c];
        }
        g_asEff0[idx] = s1; g_adEff0[idx] = s2;
    }
    for (int idx = tid; idx < 16; idx += 256) {
        int k = idx >> 2, h = idx & 3;
        float s0 = 0, s1 = 0;
        for (int c = 0; c < 64; c++) {
            s0 += We0[k * 256 + h * 64 + c] * ae0[h * 64 + c];
            s1 += We1[k * 256 + h * 64 + c] * ae1[h * 64 + c];
        }
        g_aeEff0[idx] = s0; g_aeEff1[idx] = s1;
    }
    __syncthreads();
    if (tid < 4) sm_mean[tid] = g_meanRaw[tid] / Ef;
    __syncthreads();
    if (tid < 4) {
        float s0 = 0, s1 = 0;
        for (int k = 0; k < 4; k++) {
            s0 += sm_mean[k] * g_aeEff0[k * 4 + tid];
            s1 += sm_mean[k] * g_aeEff1[k * 4 + tid];
        }
        g_selfae0[tid] = s0; g_selfae1[tid] = s1;
    }
}

// ---------------- layer 0 node transform (h fp16) — FROZEN (R7) ----------------
__global__ void k_node0(const float* __restrict__ x, const float* __restrict__ W0, int N) {
    int n = blockIdx.x;
    if (n >= N) return;
    int tid = threadIdx.x;
    float xk[5];
#pragma unroll
    for (int k = 0; k < 5; k++) xk[k] = x[n * 5 + k];
    float s = 0.f;
#pragma unroll
    for (int k = 0; k < 5; k++) s += xk[k] * W0[k * 256 + tid];
    g_hh[(size_t)n * 256 + tid] = __float2half_rn(s);
    if (tid < 8) {
        int which = tid >> 2, h = tid & 3;
        const float* eff = which ? g_adEff0 : g_asEff0;
        float a = 0.f;
#pragma unroll
        for (int k = 0; k < 5; k++) a += xk[k] * eff[k * 4 + h];
        (which ? g_ald : g_als)[n * 4 + h] = a;
    }
}

// ---------------- layer-0 edge pass fused with CSR placement ----------------
__global__ void k_edge0_place(const int* __restrict__ src, const int* __restrict__ dst,
                              const float* __restrict__ ea, int E) {
    int e = blockIdx.x * blockDim.x + threadIdx.x;
    if (e >= E) return;
    float4 v = ((const float4*)ea)[e];
    int s = src[e], d = dst[e];
    float4 as = ((const float4*)g_als)[s];
    float4 ad = ((const float4*)g_ald)[d];
    float4 p;
    float ale;
    ale = v.x * g_aeEff0[0] + v.y * g_aeEff0[4] + v.z * g_aeEff0[8] + v.w * g_aeEff0[12];
    p.x = __expf(lrelu(as.x + ad.x + ale));
    ale = v.x * g_aeEff0[1] + v.y * g_aeEff0[5] + v.z * g_aeEff0[9] + v.w * g_aeEff0[13];
    p.y = __expf(lrelu(as.y + ad.y + ale));
    ale = v.x * g_aeEff0[2] + v.y * g_aeEff0[6] + v.z * g_aeEff0[10] + v.w * g_aeEff0[14];
    p.z = __expf(lrelu(as.z + ad.z + ale));
    ale = v.x * g_aeEff0[3] + v.y * g_aeEff0[7] + v.z * g_aeEff0[11] + v.w * g_aeEff0[15];
    p.w = __expf(lrelu(as.w + ad.w + ale));
    int pos = g_offs[d] + atomicAdd(&g_cursor[d], 1);
    g_epos[e] = pos;
    g_srcPerm[pos] = s;
    ((float4*)g_p)[pos] = p;
}

// ---------------- per-edge attention weights layer 1 — FROZEN (R7) ----------------
template <int L>
__global__ void k_edge(const int* __restrict__ src, const int* __restrict__ dst,
                       const float* __restrict__ ea, int E) {
    int e = blockIdx.x * blockDim.x + threadIdx.x;
    if (e >= E) return;
    const float* aeEff = L ? g_aeEff1 : g_aeEff0;
    float4 v = ((const float4*)ea)[e];
    int s = src[e], d = dst[e];
    float4 as = ((const float4*)g_als)[s];
    float4 ad = ((const float4*)g_ald)[d];
    float4 p;
    float ale;
    ale = v.x * aeEff[0] + v.y * aeEff[4] + v.z * aeEff[8] + v.w * aeEff[12];
    p.x = __expf(lrelu(as.x + ad.x + ale));
    ale = v.x * aeEff[1] + v.y * aeEff[5] + v.z * aeEff[9] + v.w * aeEff[13];
    p.y = __expf(lrelu(as.y + ad.y + ale));
    ale = v.x * aeEff[2] + v.y * aeEff[6] + v.z * aeEff[10] + v.w * aeEff[14];
    p.z = __expf(lrelu(as.z + ad.z + ale));
    ale = v.x * aeEff[3] + v.y * aeEff[7] + v.z * aeEff[11] + v.w * aeEff[15];
    p.w = __expf(lrelu(as.w + ad.w + ale));
    ((float4*)g_p)[g_epos[e]] = p;
}

// ---------------- gather — FROZEN (R7) ----------------
template <int L>
__global__ __launch_bounds__(256) void k_gather(const float* __restrict__ b, int N) {
    int wib = threadIdx.x >> 5;
    int lane = threadIdx.x & 31;
    int n = blockIdx.x * 8 + wib;
    int hh = lane >> 3;
    bool active = (n < N);
    float o0 = 0, o1 = 0, o2 = 0, o3 = 0, o4 = 0, o5 = 0, o6 = 0, o7 = 0;
    if (active) {
        const float* selfae = L ? g_selfae1 : g_selfae0;
        float pself = __expf(lrelu(g_als[n * 4 + hh] + g_ald[n * 4 + hh] + selfae[hh]));
        float a0 = 0, a1 = 0, a2 = 0, a3 = 0, a4 = 0, a5 = 0, a6 = 0, a7 = 0;
        {
            uint4 u = ((const uint4*)(g_hh + (size_t)n * 256))[lane];
            acc8(a0, a1, a2, a3, a4, a5, a6, a7, u, pself);
        }
        float denom = pself;
        int base = g_offs[n], deg = g_deg[n];
        for (int i0 = 0; i0 < deg; i0 += 32) {
            int cnt = min(32, deg - i0);
            int sl = 0;
            if (lane < cnt) sl = g_srcPerm[base + i0 + lane];
            int j = 0;
            for (; j + 8 <= cnt; j += 8) {
                int s0 = __shfl_sync(0xFFFFFFFFu, sl, j);
                int s1 = __shfl_sync(0xFFFFFFFFu, sl, j + 1);
                int s2 = __shfl_sync(0xFFFFFFFFu, sl, j + 2);
                int s3 = __shfl_sync(0xFFFFFFFFu, sl, j + 3);
                int s4 = __shfl_sync(0xFFFFFFFFu, sl, j + 4);
                int s5 = __shfl_sync(0xFFFFFFFFu, sl, j + 5);
                int s6 = __shfl_sync(0xFFFFFFFFu, sl, j + 6);
                int s7 = __shfl_sync(0xFFFFFFFFu, sl, j + 7);
                size_t pb = (size_t)(base + i0 + j) * 4 + hh;
                float p0 = g_p[pb], p1 = g_p[pb + 4], p2 = g_p[pb + 8], p3 = g_p[pb + 12];
                float p4 = g_p[pb + 16], p5 = g_p[pb + 20], p6 = g_p[pb + 24], p7 = g_p[pb + 28];
                uint4 u0 = ((const uint4*)(g_hh + (size_t)s0 * 256))[lane];
                uint4 u1 = ((const uint4*)(g_hh + (size_t)s1 * 256))[lane];
                uint4 u2 = ((const uint4*)(g_hh + (size_t)s2 * 256))[lane];
                uint4 u3 = ((const uint4*)(g_hh + (size_t)s3 * 256))[lane];
                uint4 u4 = ((const uint4*)(g_hh + (size_t)s4 * 256))[lane];
                uint4 u5 = ((const uint4*)(g_hh + (size_t)s5 * 256))[lane];
                uint4 u6 = ((const uint4*)(g_hh + (size_t)s6 * 256))[lane];
                uint4 u7 = ((const uint4*)(g_hh + (size_t)s7 * 256))[lane];
                acc8(a0, a1, a2, a3, a4, a5, a6, a7, u0, p0);
                acc8(a0, a1, a2, a3, a4, a5, a6, a7, u1, p1);
                acc8(a0, a1, a2, a3, a4, a5, a6, a7, u2, p2);
                acc8(a0, a1, a2, a3, a4, a5, a6, a7, u3, p3);
                acc8(a0, a1, a2, a3, a4, a5, a6, a7, u4, p4);
                acc8(a0, a1, a2, a3, a4, a5, a6, a7, u5, p5);
                acc8(a0, a1, a2, a3, a4, a5, a6, a7, u6, p6);
                acc8(a0, a1, a2, a3, a4, a5, a6, a7, u7, p7);
                denom += p0 + p1 + p2 + p3 + p4 + p5 + p6 + p7;
            }
            for (; j < cnt; j++) {
                int s0 = __shfl_sync(0xFFFFFFFFu, sl, j);
                float p0 = g_p[(size_t)(base + i0 + j) * 4 + hh];
                uint4 u0 = ((const uint4*)(g_hh + (size_t)s0 * 256))[lane];
                acc8(a0, a1, a2, a3, a4, a5, a6, a7, u0, p0);
                denom += p0;
            }
        }
        float inv = 1.f / (denom + 1e-16f);
        int c = lane * 8;
        o0 = a0 * inv + b[c + 0]; o1 = a1 * inv + b[c + 1];
        o2 = a2 * inv + b[c + 2]; o3 = a3 * inv + b[c + 3];
        o4 = a4 * inv + b[c + 4]; o5 = a5 * inv + b[c + 5];
        o6 = a6 * inv + b[c + 6]; o7 = a7 * inv + b[c + 7];
        if (L == 0) {
            o0 = fmaxf(o0, 0.f); o1 = fmaxf(o1, 0.f); o2 = fmaxf(o2, 0.f); o3 = fmaxf(o3, 0.f);
            o4 = fmaxf(o4, 0.f); o5 = fmaxf(o5, 0.f); o6 = fmaxf(o6, 0.f); o7 = fmaxf(o7, 0.f);
            __half2 q0 = __floats2half2_rn(o0, o1), q1 = __floats2half2_rn(o2, o3);
            __half2 q2 = __floats2half2_rn(o4, o5), q3 = __floats2half2_rn(o6, o7);
            uint4 pk;
            pk.x = *(unsigned*)&q0; pk.y = *(unsigned*)&q1;
            pk.z = *(unsigned*)&q2; pk.w = *(unsigned*)&q3;
            ((uint4*)(g_x1h + (size_t)n * 256))[lane] = pk;
        } else {
            float* op = g_x1 + (size_t)n * 256 + c;
            ((float4*)op)[0] = make_float4(o0, o1, o2, o3);
            ((float4*)op)[1] = make_float4(o4, o5, o6, o7);
        }
    }
    if (L == 1) {
        __shared__ float tile[8 * 256];
        if (active) {
            float* tp = tile + wib * 256 + lane * 8;
            ((float4*)tp)[0] = make_float4(o0, o1, o2, o3);
            ((float4*)tp)[1] = make_float4(o4, o5, o6, o7);
        }
        __syncthreads();
        int c = threadIdx.x;
        int nb = min(8, N - blockIdx.x * 8);
        float s = 0.f, m = -FLT_MAX;
        for (int w = 0; w < nb; w++) {
            float v = tile[w * 256 + c];
            s += v;
            m = fmaxf(m, v);
        }
        g_poolSum[(size_t)blockIdx.x * 256 + c] = s;
        g_poolMax[(size_t)blockIdx.x * 256 + c] = m;
    }
}

// ---------------- layer 1 node transform: tensor-core GEMM — FROZEN (R7) ----------------
#define A_STRIDE 264
__global__ __launch_bounds__(256) void k_node1mma(int N) {
    __shared__ __align__(16) __half As[64 * A_STRIDE];
    int tid = threadIdx.x;
    int warp = tid >> 5, lane = tid & 31;
    int m0 = blockIdx.x * 64;
    for (int idx = tid; idx < 64 * 32; idx += 256) {
        int r = idx >> 5, c = idx & 31;
        int nrow = m0 + r;
        uint4 v = make_uint4(0, 0, 0, 0);
        if (nrow < N) v = ((const uint4*)(g_x1h + (size_t)nrow * 256))[c];
        *(uint4*)&As[r * A_STRIDE + c * 8] = v;
    }
    __syncthreads();

    float acc[4][4][4];
#pragma unroll
    for (int mt = 0; mt < 4; mt++)
#pragma unroll
        for (int nt = 0; nt < 4; nt++)
#pragma unroll
            for (int r = 0; r < 4; r++) acc[mt][nt][r] = 0.f;

    int nbase = warp * 32;
    for (int k0 = 0; k0 < 256; k0 += 16) {
        unsigned aR[4][4];
        int arow = lane & 15;
        int acol = k0 + ((lane >> 4) << 3);
#pragma unroll
        for (int mt = 0; mt < 4; mt++) {
            unsigned saddr =
                (unsigned)__cvta_generic_to_shared(&As[(mt * 16 + arow) * A_STRIDE + acol]);
            asm volatile("ldmatrix.sync.aligned.m8n8.x4.shared.b16 {%0,%1,%2,%3}, [%4];"
                         : "=r"(aR[mt][0]), "=r"(aR[mt][1]), "=r"(aR[mt][2]), "=r"(aR[mt][3])
                         : "r"(saddr));
        }
#pragma unroll
        for (int nt = 0; nt < 4; nt++) {
            const __half* bp =
                g_W1h + (size_t)(nbase + nt * 8 + (lane >> 2)) * 256 + k0 + ((lane & 3) << 1);
            unsigned b0 = *(const unsigned*)bp;
            unsigned b1 = *(const unsigned*)(bp + 8);
#pragma unroll
            for (int mt = 0; mt < 4; mt++)
                mma16816(acc[mt][nt][0], acc[mt][nt][1], acc[mt][nt][2], acc[mt][nt][3],
                         aR[mt][0], aR[mt][1], aR[mt][2], aR[mt][3], b0, b1);
        }
    }
#pragma unroll
    for (int mt = 0; mt < 4; mt++) {
#pragma unroll
        for (int nt = 0; nt < 4; nt++) {
            int r0 = m0 + mt * 16 + (lane >> 2);
            int cc = nbase + nt * 8 + ((lane & 3) << 1);
            if (r0 < N) {
                __half2 v = __floats2half2_rn(acc[mt][nt][0], acc[mt][nt][1]);
                *(__half2*)&g_hh[(size_t)r0 * 256 + cc] = v;
            }
            int r1 = r0 + 8;
            if (r1 < N) {
                __half2 v = __floats2half2_rn(acc[mt][nt][2], acc[mt][nt][3]);
                *(__half2*)&g_hh[(size_t)r1 * 256 + cc] = v;
            }
        }
    }
}

// ---------------- layer-1 attention logits from h1 — FROZEN (R7) ----------------
__global__ __launch_bounds__(256) void k_logits1(const float* __restrict__ as1,
                                                 const float* __restrict__ ad1, int N) {
    __shared__ float sa[256], sd[256];
    sa[threadIdx.x] = as1[threadIdx.x];
    sd[threadIdx.x] = ad1[threadIdx.x];
    __syncthreads();
    int wib = threadIdx.x >> 5, lane = threadIdx.x & 31;
    int n = blockIdx.x * 8 + wib;
    if (n >= N) return;
    int hh = lane >> 3;
    int c = lane * 8;
    uint4 u = ((const uint4*)(g_hh + (size_t)n * 256))[lane];
    float2 f0 = __half22float2(*(const __half2*)&u.x);
    float2 f1 = __half22float2(*(const __half2*)&u.y);
    float2 f2 = __half22float2(*(const __half2*)&u.z);
    float2 f3 = __half22float2(*(const __half2*)&u.w);
    float s = f0.x * sa[c] + f0.y * sa[c + 1] + f1.x * sa[c + 2] + f1.y * sa[c + 3] +
              f2.x * sa[c + 4] + f2.y * sa[c + 5] + f3.x * sa[c + 6] + f3.y * sa[c + 7];
    float d = f0.x * sd[c] + f0.y * sd[c + 1] + f1.x * sd[c + 2] + f1.y * sd[c + 3] +
              f2.x * sd[c + 4] + f2.y * sd[c + 5] + f3.x * sd[c + 6] + f3.y * sd[c + 7];
#pragma unroll
    for (int o = 4; o > 0; o >>= 1) {
        s += __shfl_xor_sync(0xFFFFFFFFu, s, o);
        d += __shfl_xor_sync(0xFFFFFFFFu, d, o);
    }
    if ((lane & 7) == 0) {
        g_als[n * 4 + hh] = s;
        g_ald[n * 4 + hh] = d;
    }
}

// ---------------- pooling finalize + tail ----------------
__global__ void k_poolfin(int NB) {
    int c = threadIdx.x;
    float s = 0.f, m = -FLT_MAX;
    for (int i = blockIdx.x; i < NB; i += gridDim.x) {
        s += g_poolSum[(size_t)i * 256 + c];
        m = fmaxf(m, g_poolMax[(size_t)i * 256 + c]);
    }
    atomicAdd(&g_meansum[c], s);
    atomicMax(&g_maxbits[c], encf(m));
}

// fused: s = (h . meansum)/N ; pn = exp(s) ; Z += pn
__global__ __launch_bounds__(256) void k_dotexp(int N) {
    __shared__ float wsum[8];
    int gw = (blockIdx.x * blockDim.x + threadIdx.x) >> 5;
    int lane = threadIdx.x & 31;
    float invN = 1.f / (float)N;
    float contrib = 0.f;
    if (gw < N) {
        float s = 0.f;
#pragma unroll
        for (int i = 0; i < 8; i++) {
            int c = lane + i * 32;
            s += g_x1[(size_t)gw * 256 + c] * g_meansum[c];
        }
#pragma unroll
        for (int o = 16; o > 0; o >>= 1) s += __shfl_down_sync(0xFFFFFFFFu, s, o);
        if (lane == 0) {
            float e = __expf(s * invN);
            g_pn[gw] = e;
            contrib = e;
        }
    }
    if (lane == 0) wsum[threadIdx.x >> 5] = contrib;
    __syncthreads();
    if (threadIdx.x < 8) {
        float v = wsum[threadIdx.x];
#pragma unroll
        for (int o = 4; o > 0; o >>= 1) v += __shfl_down_sync(0xFFu, v, o);
        if (threadIdx.x == 0) atomicAdd(&g_Z, v);
    }
}

__global__ void k_attpool(int N) {
    int c = threadIdx.x;
    int nb = blockIdx.x * 64;
    float s = 0.f;
    for (int j = 0; j < 64; j++) {
        int n = nb + j;
        if (n < N) s += g_x1[(size_t)n * 256 + c] * g_pn[n];
    }
    atomicAdd(&g_attsum[c], s);
}

__global__ void k_mlp(const float* __restrict__ Wm1, const float* __restrict__ bm1,
                      const float* __restrict__ Wm2, const float* __restrict__ bm2,
                      const float* __restrict__ Wm3, const float* __restrict__ bm3,
                      float* __restrict__ out, int N) {
    __shared__ float comb[768], z1[128], z2[64];
    int tid = threadIdx.x;
    float Zinv = 1.f / g_Z;
    comb[tid] = g_meansum[tid] / (float)N;
    comb[256 + tid] = decf(g_maxbits[tid]);
    comb[512 + tid] = g_attsum[tid] * Zinv;
    __syncthreads();
    if (tid < 128) {
        float s = bm1[tid];
        for (int k = 0; k < 768; k++) s += comb[k] * Wm1[k * 128 + tid];
        z1[tid] = fmaxf(s, 0.f);
    }
    __syncthreads();
    if (tid < 64) {
        float s = bm2[tid];
        for (int k = 0; k < 128; k++) s += z1[k] * Wm2[k * 64 + tid];
        z2[tid] = fmaxf(s, 0.f);
    }
    __syncthreads();
    if (tid < 128) {
        float s = bm3[tid];
        for (int k = 0; k < 64; k++) s += z2[k] * Wm3[k * 128 + tid];
        out[tid] = s;
    }
}

// ---------------- launch ----------------
extern "C" void kernel_launch(void* const* d_in, const int* in_sizes, int n_in,
                              void* d_out, int out_size) {
    const float* x   = (const float*)d_in[0];
    const int*   ei  = (const int*)d_in[1];
    const float* ea  = (const float*)d_in[2];
    const float* W0  = (const float*)d_in[3];
    const float* as0 = (const float*)d_in[4];
    const float* ad0 = (const float*)d_in[5];
    const float* We0 = (const float*)d_in[6];
    const float* ae0 = (const float*)d_in[7];
    const float* b0  = (const float*)d_in[8];
    const float* W1  = (const float*)d_in[9];
    const float* as1 = (const float*)d_in[10];
    const float* ad1 = (const float*)d_in[11];
    const float* We1 = (const float*)d_in[12];
    const float* ae1 = (const float*)d_in[13];
    const float* b1  = (const float*)d_in[14];
    const float* Wm1 = (const float*)d_in[15];
    const float* bm1 = (const float*)d_in[16];
    const float* Wm2 = (const float*)d_in[17];
    const float* bm2 = (const float*)d_in[18];
    const float* Wm3 = (const float*)d_in[19];
    const float* bm3 = (const float*)d_in[20];

    int N = in_sizes[0] / 5;
    int E = in_sizes[1] / 2;
    const int* src = ei;
    const int* dst = ei + E;

    int NB = (N + 1023) / 1024;
    int EB = (E + 255) / 256;
    int GB = (N + 7) / 8;

    k_zero<<<(N + 255) / 256, 256>>>(N);
    k_meanEA_deg<<<512, 256>>>(ea, dst, E);
    k_scanA<<<NB, 1024>>>(N);
    k_scanBC<<<NB, 1024>>>(NB, N);
    k_prew<<<257, 256>>>(W1, W0, as0, ad0, We0, ae0, We1, ae1, (float)E);

    // layer 0 (edge pass fused with CSR placement)
    k_node0<<<N, 256>>>(x, W0, N);
    k_edge0_place<<<EB, 256>>>(src, dst, ea, E);
    k_gather<0><<<GB, 256>>>(b0, N);

    // layer 1
    k_node1mma<<<(N + 63) / 64, 256>>>(N);
    k_logits1<<<GB, 256>>>(as1, ad1, N);
    k_edge<1><<<EB, 256>>>(src, dst, ea, E);
    k_gather<1><<<GB, 256>>>(b1, N);

    // pooling + MLP
    k_poolfin<<<64, 256>>>(GB);
    k_dotexp<<<(N * 32 + 255) / 256, 256>>>(N);
    k_attpool<<<(N + 63) / 64, 256>>>(N);
    k_mlp<<<1, 256>>>(Wm1, bm1, Wm2, bm2, Wm3, bm3, (float*)d_out, N);
}